// round 2
// baseline (speedup 1.0000x reference)
#include <cuda_runtime.h>

#define TT 256
#define HH 512

// -------- scratch (__device__ globals; no allocations allowed) --------
__device__ float g_Z [TT*HH];     // relu(h@U+a)
__device__ float g_P [TT*HH];     // Z@W+b
__device__ float g_UU[TT*HH];     // h .* Z
__device__ float g_S [TT*HH];     // inclusive prefix sum of h over t
__device__ float g_F [TT*HH];     // exclusive prefix of kappa_i * d_i
__device__ float g_G [TT*HH];     // exclusive prefix of kappa_i * S_i * d_i
__device__ float g_DE[TT*2*HH];   // [:,0:H]=D rows d_t, [:,H:2H]=S.*D
__device__ float g_M [TT*2*HH];   // C @ DE  (M1 | M2)
__device__ float g_C [TT*TT];     // strictly-lower-tri  z_t . (h_i.*z_i)
__device__ float g_kappa[TT];

// -------- block reductions (256 threads) --------
__device__ __forceinline__ float blockReduceSum256(float v, float* sb) {
    #pragma unroll
    for (int o = 16; o; o >>= 1) v += __shfl_xor_sync(0xffffffffu, v, o);
    int lane = threadIdx.x & 31, w = threadIdx.x >> 5;
    if (lane == 0) sb[w] = v;
    __syncthreads();
    if (w == 0) {
        float x = (lane < 8) ? sb[lane] : 0.f;
        #pragma unroll
        for (int o = 4; o; o >>= 1) x += __shfl_xor_sync(0xffffffffu, x, o);
        if (lane == 0) sb[8] = x;
    }
    __syncthreads();
    float r = sb[8];
    __syncthreads();
    return r;
}

__device__ __forceinline__ float blockReduceMax256(float v, float* sb) {
    #pragma unroll
    for (int o = 16; o; o >>= 1) v = fmaxf(v, __shfl_xor_sync(0xffffffffu, v, o));
    int lane = threadIdx.x & 31, w = threadIdx.x >> 5;
    if (lane == 0) sb[w] = v;
    __syncthreads();
    if (w == 0) {
        float x = (lane < 8) ? sb[lane] : -3.4e38f;
        #pragma unroll
        for (int o = 4; o; o >>= 1) x = fmaxf(x, __shfl_xor_sync(0xffffffffu, x, o));
        if (lane == 0) sb[8] = x;
    }
    __syncthreads();
    float r = sb[8];
    __syncthreads();
    return r;
}

// -------- generic 64x64x16 tiled SGEMM --------
// EPI: 0=none, 1=+bias, 2=relu(+bias), 3=strict-lower-tri mask (keep n<m)
// TB:  false -> C = A(MxK) @ B(KxN);  true -> C = A(MxK) @ B(NxK)^T
template<bool TB, int EPI>
__global__ __launch_bounds__(256)
void gemm64(const float* __restrict__ A, const float* __restrict__ B,
            const float* __restrict__ bias, float* __restrict__ C,
            int M, int N, int K)
{
    __shared__ float As[16][68];
    __shared__ float Bs[16][68];
    const int tid = threadIdx.x;
    const int bm0 = blockIdx.y * 64, bn0 = blockIdx.x * 64;
    const int tr = (tid >> 4) * 4;          // 0..60
    const int tc = (tid & 15) * 4;          // 0..60
    const int ar = tid >> 2, ac = (tid & 3) << 2;   // 64 rows x 4-float chunks
    const int bk = tid >> 4, bc = (tid & 15) << 2;  // 16 k x 64 cols (NN path)
    float acc[4][4] = {};

    for (int k0 = 0; k0 < K; k0 += 16) {
        float4 av = *reinterpret_cast<const float4*>(A + (size_t)(bm0 + ar) * K + k0 + ac);
        As[ac+0][ar] = av.x; As[ac+1][ar] = av.y; As[ac+2][ar] = av.z; As[ac+3][ar] = av.w;
        if (!TB) {
            float4 bv = *reinterpret_cast<const float4*>(B + (size_t)(k0 + bk) * N + bn0 + bc);
            Bs[bk][bc+0] = bv.x; Bs[bk][bc+1] = bv.y; Bs[bk][bc+2] = bv.z; Bs[bk][bc+3] = bv.w;
        } else {
            float4 bv = *reinterpret_cast<const float4*>(B + (size_t)(bn0 + ar) * K + k0 + ac);
            Bs[ac+0][ar] = bv.x; Bs[ac+1][ar] = bv.y; Bs[ac+2][ar] = bv.z; Bs[ac+3][ar] = bv.w;
        }
        __syncthreads();
        #pragma unroll
        for (int k = 0; k < 16; k++) {
            float a0 = As[k][tr+0], a1 = As[k][tr+1], a2 = As[k][tr+2], a3 = As[k][tr+3];
            float b0 = Bs[k][tc+0], b1 = Bs[k][tc+1], b2 = Bs[k][tc+2], b3 = Bs[k][tc+3];
            acc[0][0] += a0*b0; acc[0][1] += a0*b1; acc[0][2] += a0*b2; acc[0][3] += a0*b3;
            acc[1][0] += a1*b0; acc[1][1] += a1*b1; acc[1][2] += a1*b2; acc[1][3] += a1*b3;
            acc[2][0] += a2*b0; acc[2][1] += a2*b1; acc[2][2] += a2*b2; acc[2][3] += a2*b3;
            acc[3][0] += a3*b0; acc[3][1] += a3*b1; acc[3][2] += a3*b2; acc[3][3] += a3*b3;
        }
        __syncthreads();
    }

    #pragma unroll
    for (int i = 0; i < 4; i++) {
        int m = bm0 + tr + i;
        #pragma unroll
        for (int j = 0; j < 4; j++) {
            int n = bn0 + tc + j;
            float v = acc[i][j];
            if (EPI == 1) v += bias[n];
            if (EPI == 2) v = fmaxf(v + bias[n], 0.f);
            if (EPI == 3) v = (n < m) ? v : 0.f;
            C[(size_t)m * N + n] = v;
        }
    }
}

// -------- per-row: LN -> softmax-CE backward -> LN backward -> d_t --------
__global__ __launch_bounds__(256)
void grad_rows(const float* __restrict__ P, const float* __restrict__ h,
               const float* __restrict__ gamma, const float* __restrict__ beta,
               const int* __restrict__ tgt)
{
    __shared__ float sb[16];
    const int t = blockIdx.x;
    const int j0 = threadIdx.x, j1 = threadIdx.x + 256;
    const float* pr = P + t * HH;

    float p0 = pr[j0], p1 = pr[j1];
    float m  = blockReduceSum256(p0 + p1, sb) * (1.f / HH);
    float d0 = p0 - m, d1 = p1 - m;
    float v  = blockReduceSum256(d0*d0 + d1*d1, sb) * (1.f / HH);
    float rs = rsqrtf(v + 1e-5f);
    float x0 = d0 * rs, x1 = d1 * rs;

    float ga0 = gamma[j0], ga1 = gamma[j1];
    float y0 = x0 * ga0 + beta[j0], y1 = x1 * ga1 + beta[j1];

    float ymax = blockReduceMax256(fmaxf(y0, y1), sb);
    float e0 = expf(y0 - ymax), e1 = expf(y1 - ymax);
    float inv = 1.f / blockReduceSum256(e0 + e1, sb);

    int target = tgt[t];
    float gg0 = e0 * inv - (j0 == target ? 1.f : 0.f);
    float gg1 = e1 * inv - (j1 == target ? 1.f : 0.f);
    float gh0 = ga0 * gg0, gh1 = ga1 * gg1;

    float mg  = blockReduceSum256(gh0 + gh1, sb) * (1.f / HH);
    float mgx = blockReduceSum256(gh0*x0 + gh1*x1, sb) * (1.f / HH);

    g_DE[t*2*HH + j0] = rs * (gh0 - mg - x0 * mgx);
    g_DE[t*2*HH + j1] = rs * (gh1 - mg - x1 * mgx);

    float hv0 = h[t*HH + j0], hv1 = h[t*HH + j1];
    g_UU[t*HH + j0] = hv0 * g_Z[t*HH + j0];
    g_UU[t*HH + j1] = hv1 * g_Z[t*HH + j1];

    float ks = blockReduceSum256(hv0 + hv1, sb);
    if (threadIdx.x == 0) g_kappa[t] = ks;
}

// -------- sequential-in-t scan: S, F, G, E --------
__global__ __launch_bounds__(512)
void scan_kernel(const float* __restrict__ h)
{
    const int q = threadIdx.x;
    float sacc = 0.f, facc = 0.f, gacc = 0.f;
    #pragma unroll 4
    for (int t = 0; t < TT; t++) {
        float hv = h[t*HH + q];
        sacc += hv;
        g_S[t*HH + q] = sacc;
        float d  = g_DE[t*2*HH + q];
        float kp = g_kappa[t];
        g_F[t*HH + q] = facc;
        g_G[t*HH + q] = gacc;
        facc += kp * d;
        gacc += kp * sacc * d;
        g_DE[t*2*HH + HH + q] = sacc * d;   // E = S .* D
    }
}

// -------- assemble pre, final LayerNorm --------
__global__ __launch_bounds__(256)
void final_rows(const float* __restrict__ gamma, const float* __restrict__ beta,
                float* __restrict__ out)
{
    __shared__ float sb[16];
    const int t = blockIdx.x;
    const int j0 = threadIdx.x, j1 = threadIdx.x + 256;

    float pre0 = g_P[t*HH + j0]
               - g_S[t*HH + j0] * (g_M[t*2*HH + j0] + g_F[t*HH + j0])
               + (g_M[t*2*HH + HH + j0] + g_G[t*HH + j0]);
    float pre1 = g_P[t*HH + j1]
               - g_S[t*HH + j1] * (g_M[t*2*HH + j1] + g_F[t*HH + j1])
               + (g_M[t*2*HH + HH + j1] + g_G[t*HH + j1]);

    float m  = blockReduceSum256(pre0 + pre1, sb) * (1.f / HH);
    float d0 = pre0 - m, d1 = pre1 - m;
    float v  = blockReduceSum256(d0*d0 + d1*d1, sb) * (1.f / HH);
    float rs = rsqrtf(v + 1e-5f);

    out[t*HH + j0] = d0 * rs * gamma[j0] + beta[j0];
    out[t*HH + j1] = d1 * rs * gamma[j1] + beta[j1];
}

extern "C" void kernel_launch(void* const* d_in, const int* in_sizes, int n_in,
                              void* d_out, int out_size)
{
    const float* h     = (const float*)d_in[0];
    const float* U     = (const float*)d_in[1];
    const float* W     = (const float*)d_in[2];
    const float* a     = (const float*)d_in[3];
    const float* b     = (const float*)d_in[4];
    const float* gamma = (const float*)d_in[5];
    const float* beta  = (const float*)d_in[6];
    const int*   tgt   = (const int*)d_in[7];
    float* out = (float*)d_out;

    static float *pZ = nullptr, *pP, *pUU, *pDE, *pM, *pC;
    if (!pZ) {
        cudaGetSymbolAddress((void**)&pZ,  g_Z);
        cudaGetSymbolAddress((void**)&pP,  g_P);
        cudaGetSymbolAddress((void**)&pUU, g_UU);
        cudaGetSymbolAddress((void**)&pDE, g_DE);
        cudaGetSymbolAddress((void**)&pM,  g_M);
        cudaGetSymbolAddress((void**)&pC,  g_C);
    }

    // Z = relu(h @ U + a)
    gemm64<false,2><<<dim3(HH/64, TT/64), 256>>>(h, U, a, pZ, TT, HH, HH);
    // P = Z @ W + b
    gemm64<false,1><<<dim3(HH/64, TT/64), 256>>>(pZ, W, b, pP, TT, HH, HH);
    // d_t rows, kappa, UU = h.*Z
    grad_rows<<<TT, 256>>>(pP, h, gamma, beta, tgt);
    // S, F, G, E
    scan_kernel<<<1, 512>>>(h);
    // C[t,i] = z_t . (h_i.*z_i), strict lower triangle
    gemm64<true,3><<<dim3(TT/64, TT/64), 256>>>(pZ, pUU, nullptr, pC, TT, TT, HH);
    // M = C @ [D | S.*D]
    gemm64<false,0><<<dim3(2*HH/64, TT/64), 256>>>(pC, pDE, nullptr, pM, TT, 2*HH, TT);
    // pre = P - S.*(M1+F) + (M2+G); out = LN(pre)
    final_rows<<<TT, 256>>>(gamma, beta, out);
}

// round 4
// speedup vs baseline: 1.4627x; 1.4627x over previous
#include <cuda_runtime.h>

#define TT 256
#define HH 512
#define NCHUNK 16
#define TCH (TT/NCHUNK)   // 16 t-rows per scan chunk

// -------- scratch (__device__ globals; no allocations allowed) --------
__device__ float g_Z [TT*HH];     // relu(h@U+a)
__device__ float g_P [TT*HH];     // Z@W+b
__device__ float g_UU[TT*HH];     // h .* Z
__device__ float g_S [TT*HH];     // inclusive prefix sum of h over t
__device__ float g_DE[TT*2*HH];   // [:,0:H]=D rows d_t, [:,H:2H]=E=S.*D
__device__ float g_M [TT*2*HH];   // C' @ DE  (M1+F | M2+G)
__device__ float g_C [TT*TT];     // strict-lower-tri  z_t.(h_i.*z_i) + kappa_i
__device__ float g_kappa[TT];
__device__ float g_part[NCHUNK*HH];  // scan chunk totals

// -------- block reductions (256 threads) --------
__device__ __forceinline__ float blockReduceSum256(float v, float* sb) {
    #pragma unroll
    for (int o = 16; o; o >>= 1) v += __shfl_xor_sync(0xffffffffu, v, o);
    int lane = threadIdx.x & 31, w = threadIdx.x >> 5;
    if (lane == 0) sb[w] = v;
    __syncthreads();
    if (w == 0) {
        float x = (lane < 8) ? sb[lane] : 0.f;
        #pragma unroll
        for (int o = 4; o; o >>= 1) x += __shfl_xor_sync(0xffffffffu, x, o);
        if (lane == 0) sb[8] = x;
    }
    __syncthreads();
    float r = sb[8];
    __syncthreads();
    return r;
}

__device__ __forceinline__ float blockReduceMax256(float v, float* sb) {
    #pragma unroll
    for (int o = 16; o; o >>= 1) v = fmaxf(v, __shfl_xor_sync(0xffffffffu, v, o));
    int lane = threadIdx.x & 31, w = threadIdx.x >> 5;
    if (lane == 0) sb[w] = v;
    __syncthreads();
    if (w == 0) {
        float x = (lane < 8) ? sb[lane] : -3.4e38f;
        #pragma unroll
        for (int o = 4; o; o >>= 1) x = fmaxf(x, __shfl_xor_sync(0xffffffffu, x, o));
        if (lane == 0) sb[8] = x;
    }
    __syncthreads();
    float r = sb[8];
    __syncthreads();
    return r;
}

// -------- generic 64x64x16 tiled SGEMM --------
// EPI: 0=none, 1=+bias, 2=relu(+bias), 3=strict-lower-tri: v+bias[n] if n<m else 0
// TB:  false -> C = A(MxK) @ B(KxN);  true -> C = A(MxK) @ B(NxK)^T
template<bool TB, int EPI>
__global__ __launch_bounds__(256)
void gemm64(const float* __restrict__ A, const float* __restrict__ B,
            const float* __restrict__ bias, float* __restrict__ C,
            int M, int N, int K)
{
    __shared__ float As[16][68];
    __shared__ float Bs[16][68];
    const int tid = threadIdx.x;
    const int bm0 = blockIdx.y * 64, bn0 = blockIdx.x * 64;
    const int tr = (tid >> 4) * 4;
    const int tc = (tid & 15) * 4;
    const int ar = tid >> 2, ac = (tid & 3) << 2;
    const int bk = tid >> 4, bc = (tid & 15) << 2;
    float acc[4][4] = {};

    for (int k0 = 0; k0 < K; k0 += 16) {
        float4 av = *reinterpret_cast<const float4*>(A + (size_t)(bm0 + ar) * K + k0 + ac);
        As[ac+0][ar] = av.x; As[ac+1][ar] = av.y; As[ac+2][ar] = av.z; As[ac+3][ar] = av.w;
        if (!TB) {
            float4 bv = *reinterpret_cast<const float4*>(B + (size_t)(k0 + bk) * N + bn0 + bc);
            Bs[bk][bc+0] = bv.x; Bs[bk][bc+1] = bv.y; Bs[bk][bc+2] = bv.z; Bs[bk][bc+3] = bv.w;
        } else {
            float4 bv = *reinterpret_cast<const float4*>(B + (size_t)(bn0 + ar) * K + k0 + ac);
            Bs[ac+0][ar] = bv.x; Bs[ac+1][ar] = bv.y; Bs[ac+2][ar] = bv.z; Bs[ac+3][ar] = bv.w;
        }
        __syncthreads();
        #pragma unroll
        for (int k = 0; k < 16; k++) {
            float a0 = As[k][tr+0], a1 = As[k][tr+1], a2 = As[k][tr+2], a3 = As[k][tr+3];
            float b0 = Bs[k][tc+0], b1 = Bs[k][tc+1], b2 = Bs[k][tc+2], b3 = Bs[k][tc+3];
            acc[0][0] += a0*b0; acc[0][1] += a0*b1; acc[0][2] += a0*b2; acc[0][3] += a0*b3;
            acc[1][0] += a1*b0; acc[1][1] += a1*b1; acc[1][2] += a1*b2; acc[1][3] += a1*b3;
            acc[2][0] += a2*b0; acc[2][1] += a2*b1; acc[2][2] += a2*b2; acc[2][3] += a2*b3;
            acc[3][0] += a3*b0; acc[3][1] += a3*b1; acc[3][2] += a3*b2; acc[3][3] += a3*b3;
        }
        __syncthreads();
    }

    #pragma unroll
    for (int i = 0; i < 4; i++) {
        int m = bm0 + tr + i;
        #pragma unroll
        for (int j = 0; j < 4; j++) {
            int n = bn0 + tc + j;
            float v = acc[i][j];
            if (EPI == 1) v += bias[n];
            if (EPI == 2) v = fmaxf(v + bias[n], 0.f);
            if (EPI == 3) v = (n < m) ? (v + bias[n]) : 0.f;
            C[(size_t)m * N + n] = v;
        }
    }
}

// -------- per-row: LN -> softmax-CE backward -> LN backward -> d_t --------
__global__ __launch_bounds__(256)
void grad_rows(const float* __restrict__ P, const float* __restrict__ h,
               const float* __restrict__ gamma, const float* __restrict__ beta,
               const int* __restrict__ tgt)
{
    __shared__ float sb[16];
    const int t = blockIdx.x;
    const int j0 = threadIdx.x, j1 = threadIdx.x + 256;
    const float* pr = P + t * HH;

    float p0 = pr[j0], p1 = pr[j1];
    float m  = blockReduceSum256(p0 + p1, sb) * (1.f / HH);
    float d0 = p0 - m, d1 = p1 - m;
    float v  = blockReduceSum256(d0*d0 + d1*d1, sb) * (1.f / HH);
    float rs = rsqrtf(v + 1e-5f);
    float x0 = d0 * rs, x1 = d1 * rs;

    float ga0 = gamma[j0], ga1 = gamma[j1];
    float y0 = x0 * ga0 + beta[j0], y1 = x1 * ga1 + beta[j1];

    float ymax = blockReduceMax256(fmaxf(y0, y1), sb);
    float e0 = expf(y0 - ymax), e1 = expf(y1 - ymax);
    float inv = 1.f / blockReduceSum256(e0 + e1, sb);

    int target = tgt[t];
    float gg0 = e0 * inv - (j0 == target ? 1.f : 0.f);
    float gg1 = e1 * inv - (j1 == target ? 1.f : 0.f);
    float gh0 = ga0 * gg0, gh1 = ga1 * gg1;

    float mg  = blockReduceSum256(gh0 + gh1, sb) * (1.f / HH);
    float mgx = blockReduceSum256(gh0*x0 + gh1*x1, sb) * (1.f / HH);

    g_DE[t*2*HH + j0] = rs * (gh0 - mg - x0 * mgx);
    g_DE[t*2*HH + j1] = rs * (gh1 - mg - x1 * mgx);

    float hv0 = h[t*HH + j0], hv1 = h[t*HH + j1];
    g_UU[t*HH + j0] = hv0 * g_Z[t*HH + j0];
    g_UU[t*HH + j1] = hv1 * g_Z[t*HH + j1];

    float ks = blockReduceSum256(hv0 + hv1, sb);
    if (threadIdx.x == 0) g_kappa[t] = ks;
}

// -------- parallel cumsum over t, pass A: local prefix + chunk totals --------
// grid: (HH/128, NCHUNK), block 128. Thread owns one column within a chunk.
__global__ __launch_bounds__(128)
void scanA(const float* __restrict__ h)
{
    const int q  = blockIdx.x * 128 + threadIdx.x;
    const int t0 = blockIdx.y * TCH;
    float acc = 0.f;
    #pragma unroll
    for (int tt = 0; tt < TCH; tt++) {
        acc += h[(t0 + tt) * HH + q];
        g_S[(t0 + tt) * HH + q] = acc;
    }
    g_part[blockIdx.y * HH + q] = acc;
}

// -------- pass B: add chunk offsets, write E = S .* D --------
__global__ __launch_bounds__(128)
void scanB()
{
    const int q  = blockIdx.x * 128 + threadIdx.x;
    const int cb = blockIdx.y;
    const int t0 = cb * TCH;
    float off = 0.f;
    for (int c = 0; c < cb; c++) off += g_part[c * HH + q];
    #pragma unroll
    for (int tt = 0; tt < TCH; tt++) {
        int t = t0 + tt;
        float s = g_S[t * HH + q] + off;
        g_S[t * HH + q] = s;
        g_DE[t*2*HH + HH + q] = s * g_DE[t*2*HH + q];
    }
}

// -------- assemble pre, final LayerNorm --------
__global__ __launch_bounds__(256)
void final_rows(const float* __restrict__ gamma, const float* __restrict__ beta,
                float* __restrict__ out)
{
    __shared__ float sb[16];
    const int t = blockIdx.x;
    const int j0 = threadIdx.x, j1 = threadIdx.x + 256;

    float pre0 = g_P[t*HH + j0]
               - g_S[t*HH + j0] * g_M[t*2*HH + j0]
               + g_M[t*2*HH + HH + j0];
    float pre1 = g_P[t*HH + j1]
               - g_S[t*HH + j1] * g_M[t*2*HH + j1]
               + g_M[t*2*HH + HH + j1];

    float m  = blockReduceSum256(pre0 + pre1, sb) * (1.f / HH);
    float d0 = pre0 - m, d1 = pre1 - m;
    float v  = blockReduceSum256(d0*d0 + d1*d1, sb) * (1.f / HH);
    float rs = rsqrtf(v + 1e-5f);

    out[t*HH + j0] = d0 * rs * gamma[j0] + beta[j0];
    out[t*HH + j1] = d1 * rs * gamma[j1] + beta[j1];
}

extern "C" void kernel_launch(void* const* d_in, const int* in_sizes, int n_in,
                              void* d_out, int out_size)
{
    const float* h     = (const float*)d_in[0];
    const float* U     = (const float*)d_in[1];
    const float* W     = (const float*)d_in[2];
    const float* a     = (const float*)d_in[3];
    const float* b     = (const float*)d_in[4];
    const float* gamma = (const float*)d_in[5];
    const float* beta  = (const float*)d_in[6];
    const int*   tgt   = (const int*)d_in[7];
    float* out = (float*)d_out;

    static float *pZ = nullptr, *pP, *pUU, *pDE, *pM, *pC, *pKap;
    if (!pZ) {
        cudaGetSymbolAddress((void**)&pZ,   g_Z);
        cudaGetSymbolAddress((void**)&pP,   g_P);
        cudaGetSymbolAddress((void**)&pUU,  g_UU);
        cudaGetSymbolAddress((void**)&pDE,  g_DE);
        cudaGetSymbolAddress((void**)&pM,   g_M);
        cudaGetSymbolAddress((void**)&pC,   g_C);
        cudaGetSymbolAddress((void**)&pKap, g_kappa);
    }

    // Z = relu(h @ U + a)
    gemm64<false,2><<<dim3(HH/64, TT/64), 256>>>(h, U, a, pZ, TT, HH, HH);
    // P = Z @ W + b
    gemm64<false,1><<<dim3(HH/64, TT/64), 256>>>(pZ, W, b, pP, TT, HH, HH);
    // d_t rows, kappa, UU = h.*Z
    grad_rows<<<TT, 256>>>(pP, h, gamma, beta, tgt);
    // S = cumsum(h) (two-pass), E = S.*D
    scanA<<<dim3(HH/128, NCHUNK), 128>>>(h);
    scanB<<<dim3(HH/128, NCHUNK), 128>>>();
    // C'[t,i] = z_t.(h_i.*z_i) + kappa_i, strict lower triangle
    gemm64<true,3><<<dim3(TT/64, TT/64), 256>>>(pZ, pUU, pKap, pC, TT, TT, HH);
    // M = C' @ [D | E]  -> (M1+F | M2+G)
    gemm64<false,0><<<dim3(2*HH/64, TT/64), 256>>>(pC, pDE, nullptr, pM, TT, 2*HH, TT);
    // pre = P - S.*M1 + M2; out = LN(pre)
    final_rows<<<TT, 256>>>(gamma, beta, out);
}

// round 10
// speedup vs baseline: 3.1268x; 2.1377x over previous
#include <cuda_runtime.h>

#define TT 256
#define HH 512
#define NCHUNK 32
#define TCH (TT/NCHUNK)   // 8 t-rows per scan chunk

typedef unsigned long long ull;

// -------- scratch (__device__ globals; no allocations allowed) --------
__device__ float g_Z [TT*HH];       // relu(h@U+a)
__device__ float g_P [TT*HH];       // Z@W+b
__device__ float g_UU[TT*HH];       // h .* Z
__device__ float g_S [TT*HH];       // inclusive prefix sum of h over t
__device__ float g_DE[TT*2*HH];     // [:,0:H]=D rows d_t, [:,H:2H]=E=S.*D
__device__ float g_M [TT*2*HH];     // C' @ DE  (M1+F | M2+G)
__device__ float g_C [TT*TT];       // strict-lower-tri z_t.(h_i.*z_i) + kappa_i
__device__ float g_kappa[TT];
__device__ float g_part[NCHUNK*HH]; // scan chunk totals
__device__ float g_sp [4*TT*HH];    // split-K partials for Z / P gemms (2MB)
__device__ float g_spC[8*TT*TT];    // split-K partials for C gemm (2MB)

// -------- f32x2 helpers --------
__device__ __forceinline__ void ffma2(ull& acc, ull a2, ull b2) {
    asm("fma.rn.f32x2 %0, %1, %2, %0;" : "+l"(acc) : "l"(a2), "l"(b2));
}
__device__ __forceinline__ ull dup2(float a) {
    ull r; asm("mov.b64 %0, {%1, %1};" : "=l"(r) : "f"(a)); return r;
}
__device__ __forceinline__ void unpack2(ull v, float& lo, float& hi) {
    asm("mov.b64 {%0, %1}, %2;" : "=f"(lo), "=f"(hi) : "l"(v));
}

// -------- block reductions (256 threads) --------
__device__ __forceinline__ float blockReduceSum256(float v, float* sb) {
    #pragma unroll
    for (int o = 16; o; o >>= 1) v += __shfl_xor_sync(0xffffffffu, v, o);
    int lane = threadIdx.x & 31, w = threadIdx.x >> 5;
    if (lane == 0) sb[w] = v;
    __syncthreads();
    if (w == 0) {
        float x = (lane < 8) ? sb[lane] : 0.f;
        #pragma unroll
        for (int o = 4; o; o >>= 1) x += __shfl_xor_sync(0xffffffffu, x, o);
        if (lane == 0) sb[8] = x;
    }
    __syncthreads();
    float r = sb[8];
    __syncthreads();
    return r;
}

__device__ __forceinline__ float blockReduceMax256(float v, float* sb) {
    #pragma unroll
    for (int o = 16; o; o >>= 1) v = fmaxf(v, __shfl_xor_sync(0xffffffffu, v, o));
    int lane = threadIdx.x & 31, w = threadIdx.x >> 5;
    if (lane == 0) sb[w] = v;
    __syncthreads();
    if (w == 0) {
        float x = (lane < 8) ? sb[lane] : -3.4e38f;
        #pragma unroll
        for (int o = 4; o; o >>= 1) x = fmaxf(x, __shfl_xor_sync(0xffffffffu, x, o));
        if (lane == 0) sb[8] = x;
    }
    __syncthreads();
    float r = sb[8];
    __syncthreads();
    return r;
}

// -------- 64x64 tile SGEMM using fma.rn.f32x2, optional split-K over blockIdx.z --------
// TB: false -> A(MxK)@B(KxN); true -> A(MxK)@B(NxK)^T
// Writes raw partial/output tile to Cout + blockIdx.z*M*N (no epilogue).
template<bool TB>
__global__ __launch_bounds__(256)
void gemm_f2(const float* __restrict__ A, const float* __restrict__ B,
             float* __restrict__ Cout, int M, int N, int K, int Kc)
{
    __shared__ float As[16][68];
    __shared__ float Bs[16][68];
    const int tid = threadIdx.x;
    const int bm0 = blockIdx.y * 64, bn0 = blockIdx.x * 64;
    const int tr = (tid >> 4) * 4;
    const int tc = (tid & 15) * 4;
    const int ar = tid >> 2, ac = (tid & 3) << 2;
    const int bk = tid >> 4, bc = (tid & 15) << 2;
    const int kbeg = blockIdx.z * Kc, kend = kbeg + Kc;

    ull acc[4][2];
    #pragma unroll
    for (int i = 0; i < 4; i++) { acc[i][0] = 0ull; acc[i][1] = 0ull; }

    for (int k0 = kbeg; k0 < kend; k0 += 16) {
        float4 av = *reinterpret_cast<const float4*>(A + (size_t)(bm0 + ar) * K + k0 + ac);
        As[ac+0][ar] = av.x; As[ac+1][ar] = av.y; As[ac+2][ar] = av.z; As[ac+3][ar] = av.w;
        if (!TB) {
            float4 bv = *reinterpret_cast<const float4*>(B + (size_t)(k0 + bk) * N + bn0 + bc);
            *reinterpret_cast<float4*>(&Bs[bk][bc]) = bv;
        } else {
            float4 bv = *reinterpret_cast<const float4*>(B + (size_t)(bn0 + ar) * K + k0 + ac);
            Bs[ac+0][ar] = bv.x; Bs[ac+1][ar] = bv.y; Bs[ac+2][ar] = bv.z; Bs[ac+3][ar] = bv.w;
        }
        __syncthreads();
        #pragma unroll
        for (int k = 0; k < 16; k++) {
            float4 a4 = *reinterpret_cast<const float4*>(&As[k][tr]);
            ull b01 = *reinterpret_cast<const ull*>(&Bs[k][tc]);
            ull b23 = *reinterpret_cast<const ull*>(&Bs[k][tc+2]);
            ull a0 = dup2(a4.x), a1 = dup2(a4.y), a2 = dup2(a4.z), a3 = dup2(a4.w);
            ffma2(acc[0][0], a0, b01); ffma2(acc[0][1], a0, b23);
            ffma2(acc[1][0], a1, b01); ffma2(acc[1][1], a1, b23);
            ffma2(acc[2][0], a2, b01); ffma2(acc[2][1], a2, b23);
            ffma2(acc[3][0], a3, b01); ffma2(acc[3][1], a3, b23);
        }
        __syncthreads();
    }

    float* Cp = Cout + (size_t)blockIdx.z * M * N;
    #pragma unroll
    for (int i = 0; i < 4; i++) {
        int m = bm0 + tr + i;
        float v0, v1, v2, v3;
        unpack2(acc[i][0], v0, v1);
        unpack2(acc[i][1], v2, v3);
        float4 o = make_float4(v0, v1, v2, v3);
        *reinterpret_cast<float4*>(Cp + (size_t)m * N + bn0 + tc) = o;
    }
}

// -------- split-K reduce + epilogue for Z: relu(.+a), also UU = h.*Z --------
__global__ __launch_bounds__(256)
void reduceZ(const float* __restrict__ h, const float* __restrict__ a)
{
    int idx = blockIdx.x * 256 + threadIdx.x;     // float4 index, 32768 total
    int e = idx * 4;
    int col = e & (HH - 1);
    float4 s0 = *reinterpret_cast<const float4*>(g_sp + e);
    float4 s1 = *reinterpret_cast<const float4*>(g_sp + TT*HH + e);
    float4 s2 = *reinterpret_cast<const float4*>(g_sp + 2*TT*HH + e);
    float4 s3 = *reinterpret_cast<const float4*>(g_sp + 3*TT*HH + e);
    float4 bi = *reinterpret_cast<const float4*>(a + col);
    float4 hv = *reinterpret_cast<const float4*>(h + e);
    float4 z;
    z.x = fmaxf(s0.x + s1.x + s2.x + s3.x + bi.x, 0.f);
    z.y = fmaxf(s0.y + s1.y + s2.y + s3.y + bi.y, 0.f);
    z.z = fmaxf(s0.z + s1.z + s2.z + s3.z + bi.z, 0.f);
    z.w = fmaxf(s0.w + s1.w + s2.w + s3.w + bi.w, 0.f);
    *reinterpret_cast<float4*>(g_Z + e) = z;
    float4 u = make_float4(hv.x*z.x, hv.y*z.y, hv.z*z.z, hv.w*z.w);
    *reinterpret_cast<float4*>(g_UU + e) = u;
}

// -------- split-K reduce + bias for P --------
__global__ __launch_bounds__(256)
void reduceP(const float* __restrict__ b)
{
    int idx = blockIdx.x * 256 + threadIdx.x;
    int e = idx * 4;
    int col = e & (HH - 1);
    float4 s0 = *reinterpret_cast<const float4*>(g_sp + e);
    float4 s1 = *reinterpret_cast<const float4*>(g_sp + TT*HH + e);
    float4 s2 = *reinterpret_cast<const float4*>(g_sp + 2*TT*HH + e);
    float4 s3 = *reinterpret_cast<const float4*>(g_sp + 3*TT*HH + e);
    float4 bi = *reinterpret_cast<const float4*>(b + col);
    float4 p;
    p.x = s0.x + s1.x + s2.x + s3.x + bi.x;
    p.y = s0.y + s1.y + s2.y + s3.y + bi.y;
    p.z = s0.z + s1.z + s2.z + s3.z + bi.z;
    p.w = s0.w + s1.w + s2.w + s3.w + bi.w;
    *reinterpret_cast<float4*>(g_P + e) = p;
}

// -------- split-K reduce for C: strict-lower mask + kappa --------
__global__ __launch_bounds__(256)
void reduceC()
{
    int idx = blockIdx.x * 256 + threadIdx.x;    // float4 index, 16384 total
    int e = idx * 4;
    int m = e >> 8;               // /TT
    int n0 = e & (TT - 1);
    float4 s = *reinterpret_cast<const float4*>(g_spC + e);
    #pragma unroll
    for (int sp = 1; sp < 8; sp++) {
        float4 t = *reinterpret_cast<const float4*>(g_spC + (size_t)sp*TT*TT + e);
        s.x += t.x; s.y += t.y; s.z += t.z; s.w += t.w;
    }
    float4 kp = *reinterpret_cast<const float4*>(g_kappa + n0);
    float4 o;
    o.x = (n0+0 < m) ? (s.x + kp.x) : 0.f;
    o.y = (n0+1 < m) ? (s.y + kp.y) : 0.f;
    o.z = (n0+2 < m) ? (s.z + kp.z) : 0.f;
    o.w = (n0+3 < m) ? (s.w + kp.w) : 0.f;
    *reinterpret_cast<float4*>(g_C + e) = o;
}

// -------- per-row: LN -> softmax-CE backward -> LN backward -> d_t, kappa --------
__global__ __launch_bounds__(256)
void grad_rows(const float* __restrict__ P, const float* __restrict__ h,
               const float* __restrict__ gamma, const float* __restrict__ beta,
               const int* __restrict__ tgt)
{
    __shared__ float sb[16];
    const int t = blockIdx.x;
    const int j0 = threadIdx.x, j1 = threadIdx.x + 256;
    const float* pr = P + t * HH;

    float p0 = pr[j0], p1 = pr[j1];
    float m  = blockReduceSum256(p0 + p1, sb) * (1.f / HH);
    float d0 = p0 - m, d1 = p1 - m;
    float v  = blockReduceSum256(d0*d0 + d1*d1, sb) * (1.f / HH);
    float rs = rsqrtf(v + 1e-5f);
    float x0 = d0 * rs, x1 = d1 * rs;

    float ga0 = gamma[j0], ga1 = gamma[j1];
    float y0 = x0 * ga0 + beta[j0], y1 = x1 * ga1 + beta[j1];

    float ymax = blockReduceMax256(fmaxf(y0, y1), sb);
    float e0 = expf(y0 - ymax), e1 = expf(y1 - ymax);
    float inv = 1.f / blockReduceSum256(e0 + e1, sb);

    int target = tgt[t];
    float gg0 = e0 * inv - (j0 == target ? 1.f : 0.f);
    float gg1 = e1 * inv - (j1 == target ? 1.f : 0.f);
    float gh0 = ga0 * gg0, gh1 = ga1 * gg1;

    float mg  = blockReduceSum256(gh0 + gh1, sb) * (1.f / HH);
    float mgx = blockReduceSum256(gh0*x0 + gh1*x1, sb) * (1.f / HH);

    g_DE[t*2*HH + j0] = rs * (gh0 - mg - x0 * mgx);
    g_DE[t*2*HH + j1] = rs * (gh1 - mg - x1 * mgx);

    float hv0 = h[t*HH + j0], hv1 = h[t*HH + j1];
    float ks = blockReduceSum256(hv0 + hv1, sb);
    if (threadIdx.x == 0) g_kappa[t] = ks;
}

// -------- parallel cumsum over t, pass A: local prefix + chunk totals --------
__global__ __launch_bounds__(128)
void scanA(const float* __restrict__ h)
{
    const int q  = blockIdx.x * 128 + threadIdx.x;
    const int t0 = blockIdx.y * TCH;
    float acc = 0.f;
    #pragma unroll
    for (int tt = 0; tt < TCH; tt++) {
        acc += h[(t0 + tt) * HH + q];
        g_S[(t0 + tt) * HH + q] = acc;
    }
    g_part[blockIdx.y * HH + q] = acc;
}

// -------- pass B: add chunk offsets, write E = S .* D --------
__global__ __launch_bounds__(128)
void scanB()
{
    const int q  = blockIdx.x * 128 + threadIdx.x;
    const int cb = blockIdx.y;
    const int t0 = cb * TCH;
    float off = 0.f;
    for (int c = 0; c < cb; c++) off += g_part[c * HH + q];
    #pragma unroll
    for (int tt = 0; tt < TCH; tt++) {
        int t = t0 + tt;
        float s = g_S[t * HH + q] + off;
        g_S[t * HH + q] = s;
        g_DE[t*2*HH + HH + q] = s * g_DE[t*2*HH + q];
    }
}

// -------- assemble pre, final LayerNorm --------
__global__ __launch_bounds__(256)
void final_rows(const float* __restrict__ gamma, const float* __restrict__ beta,
                float* __restrict__ out)
{
    __shared__ float sb[16];
    const int t = blockIdx.x;
    const int j0 = threadIdx.x, j1 = threadIdx.x + 256;

    float pre0 = g_P[t*HH + j0]
               - g_S[t*HH + j0] * g_M[t*2*HH + j0]
               + g_M[t*2*HH + HH + j0];
    float pre1 = g_P[t*HH + j1]
               - g_S[t*HH + j1] * g_M[t*2*HH + j1]
               + g_M[t*2*HH + HH + j1];

    float m  = blockReduceSum256(pre0 + pre1, sb) * (1.f / HH);
    float d0 = pre0 - m, d1 = pre1 - m;
    float v  = blockReduceSum256(d0*d0 + d1*d1, sb) * (1.f / HH);
    float rs = rsqrtf(v + 1e-5f);

    out[t*HH + j0] = d0 * rs * gamma[j0] + beta[j0];
    out[t*HH + j1] = d1 * rs * gamma[j1] + beta[j1];
}

extern "C" void kernel_launch(void* const* d_in, const int* in_sizes, int n_in,
                              void* d_out, int out_size)
{
    const float* h     = (const float*)d_in[0];
    const float* U     = (const float*)d_in[1];
    const float* W     = (const float*)d_in[2];
    const float* a     = (const float*)d_in[3];
    const float* b     = (const float*)d_in[4];
    const float* gamma = (const float*)d_in[5];
    const float* beta  = (const float*)d_in[6];
    const int*   tgt   = (const int*)d_in[7];
    float* out = (float*)d_out;

    static float *pZ = nullptr, *pP, *pUU, *pDE, *pM, *pC, *pSp, *pSpC;
    if (!pZ) {
        cudaGetSymbolAddress((void**)&pZ,   g_Z);
        cudaGetSymbolAddress((void**)&pP,   g_P);
        cudaGetSymbolAddress((void**)&pUU,  g_UU);
        cudaGetSymbolAddress((void**)&pDE,  g_DE);
        cudaGetSymbolAddress((void**)&pM,   g_M);
        cudaGetSymbolAddress((void**)&pC,   g_C);
        cudaGetSymbolAddress((void**)&pSp,  g_sp);
        cudaGetSymbolAddress((void**)&pSpC, g_spC);
    }

    // Z = relu(h @ U + a): split-K 4 -> 128 blocks, then reduce (+ UU = h.*Z)
    gemm_f2<false><<<dim3(HH/64, TT/64, 4), 256>>>(h, U, pSp, TT, HH, HH, HH/4);
    reduceZ<<<128, 256>>>(h, a);
    // C partials: z_t.(h_i.*z_i), split-K 8 -> 128 blocks (depends only on Z, UU)
    gemm_f2<true><<<dim3(TT/64, TT/64, 8), 256>>>(pZ, pUU, pSpC, TT, TT, HH, HH/8);
    // P = Z @ W + b: split-K 4 -> 128 blocks, then reduce
    gemm_f2<false><<<dim3(HH/64, TT/64, 4), 256>>>(pZ, W, pSp, TT, HH, HH, HH/4);
    reduceP<<<128, 256>>>(b);
    // d_t rows, kappa
    grad_rows<<<TT, 256>>>(pP, h, gamma, beta, tgt);
    // S = cumsum(h) (two-pass), E = S.*D
    scanA<<<dim3(HH/128, NCHUNK), 128>>>(h);
    scanB<<<dim3(HH/128, NCHUNK), 128>>>();
    // C' = mask(sum partials) + kappa (needs kappa from grad_rows)
    reduceC<<<64, 256>>>();
    // M = C' @ [D | E]  (direct, 64 blocks, K=256)
    gemm_f2<false><<<dim3(2*HH/64, TT/64, 1), 256>>>(pC, pDE, pM, TT, 2*HH, TT, TT);
    // pre = P - S.*M1 + M2; out = LN(pre)
    final_rows<<<TT, 256>>>(gamma, beta, out);
}

// round 11
// speedup vs baseline: 3.7534x; 1.2004x over previous
#include <cuda_runtime.h>

#define TT 256
#define HH 512
#define NCHUNK 32
#define TCH (TT/NCHUNK)   // 8 t-rows per scan chunk

typedef unsigned long long ull;

// -------- scratch (__device__ globals; no allocations allowed) --------
__device__ float g_Z [TT*HH];       // relu(h@U+a)
__device__ float g_P [TT*HH];       // Z@W+b
__device__ float g_UU[TT*HH];       // h .* Z
__device__ float g_S [TT*HH];       // inclusive prefix sum of h over t
__device__ float g_DE[TT*2*HH];     // [:,0:H]=D rows d_t, [:,H:2H]=E=S.*D
__device__ float g_M [TT*2*HH];     // C' @ DE  (M1+F | M2+G)
__device__ float g_C [TT*TT];       // strict-lower-tri z_t.(h_i.*z_i) + kappa_i
__device__ float g_kappa[TT];
__device__ float g_part[NCHUNK*HH]; // scan chunk totals
__device__ float g_sp [8*TT*HH];    // split-K partials for Z/P (8x) and M (4x, reused) - 4MB
__device__ float g_spC[16*TT*TT];   // split-K partials for C gemm (16x) - 4MB

// -------- f32x2 helpers --------
__device__ __forceinline__ void ffma2(ull& acc, ull a2, ull b2) {
    asm("fma.rn.f32x2 %0, %1, %2, %0;" : "+l"(acc) : "l"(a2), "l"(b2));
}
__device__ __forceinline__ ull dup2(float a) {
    ull r; asm("mov.b64 %0, {%1, %1};" : "=l"(r) : "f"(a)); return r;
}
__device__ __forceinline__ void unpack2(ull v, float& lo, float& hi) {
    asm("mov.b64 {%0, %1}, %2;" : "=f"(lo), "=f"(hi) : "l"(v));
}

// -------- block reductions (256 threads) --------
__device__ __forceinline__ float blockReduceSum256(float v, float* sb) {
    #pragma unroll
    for (int o = 16; o; o >>= 1) v += __shfl_xor_sync(0xffffffffu, v, o);
    int lane = threadIdx.x & 31, w = threadIdx.x >> 5;
    if (lane == 0) sb[w] = v;
    __syncthreads();
    if (w == 0) {
        float x = (lane < 8) ? sb[lane] : 0.f;
        #pragma unroll
        for (int o = 4; o; o >>= 1) x += __shfl_xor_sync(0xffffffffu, x, o);
        if (lane == 0) sb[8] = x;
    }
    __syncthreads();
    float r = sb[8];
    __syncthreads();
    return r;
}

__device__ __forceinline__ float blockReduceMax256(float v, float* sb) {
    #pragma unroll
    for (int o = 16; o; o >>= 1) v = fmaxf(v, __shfl_xor_sync(0xffffffffu, v, o));
    int lane = threadIdx.x & 31, w = threadIdx.x >> 5;
    if (lane == 0) sb[w] = v;
    __syncthreads();
    if (w == 0) {
        float x = (lane < 8) ? sb[lane] : -3.4e38f;
        #pragma unroll
        for (int o = 4; o; o >>= 1) x = fmaxf(x, __shfl_xor_sync(0xffffffffu, x, o));
        if (lane == 0) sb[8] = x;
    }
    __syncthreads();
    float r = sb[8];
    __syncthreads();
    return r;
}

// -------- 64x64 tile SGEMM, f32x2 FFMA, double-buffered smem, split-K over z --------
// TB: false -> A(MxK)@B(KxN); true -> A(MxK)@B(NxK)^T
// Writes raw partial tile to Cout + blockIdx.z*M*N.
template<bool TB>
__global__ __launch_bounds__(256, 2)
void gemm_f2(const float* __restrict__ A, const float* __restrict__ B,
             float* __restrict__ Cout, int M, int N, int K, int Kc)
{
    __shared__ float As[2][16][68];
    __shared__ float Bs[2][16][68];
    const int tid = threadIdx.x;
    const int bm0 = blockIdx.y * 64, bn0 = blockIdx.x * 64;
    const int tr = (tid >> 4) * 4;
    const int tc = (tid & 15) * 4;
    const int ar = tid >> 2, ac = (tid & 3) << 2;
    const int bk = tid >> 4, bc = (tid & 15) << 2;
    const int kbeg = blockIdx.z * Kc;
    const int NT = Kc >> 4;                 // 16-wide k tiles

    ull acc[4][2];
    #pragma unroll
    for (int i = 0; i < 4; i++) { acc[i][0] = 0ull; acc[i][1] = 0ull; }

    // prefetch tile 0 straight into smem buffer 0
    {
        float4 av = *reinterpret_cast<const float4*>(A + (size_t)(bm0 + ar) * K + kbeg + ac);
        As[0][ac+0][ar] = av.x; As[0][ac+1][ar] = av.y; As[0][ac+2][ar] = av.z; As[0][ac+3][ar] = av.w;
        if (!TB) {
            float4 bv = *reinterpret_cast<const float4*>(B + (size_t)(kbeg + bk) * N + bn0 + bc);
            *reinterpret_cast<float4*>(&Bs[0][bk][bc]) = bv;
        } else {
            float4 bv = *reinterpret_cast<const float4*>(B + (size_t)(bn0 + ar) * K + kbeg + ac);
            Bs[0][ac+0][ar] = bv.x; Bs[0][ac+1][ar] = bv.y; Bs[0][ac+2][ar] = bv.z; Bs[0][ac+3][ar] = bv.w;
        }
    }

    int buf = 0;
    for (int it = 0; it < NT; it++) {
        __syncthreads();
        float4 av2, bv2;
        const bool more = (it + 1 < NT);
        if (more) {
            int k0 = kbeg + (it + 1) * 16;
            av2 = *reinterpret_cast<const float4*>(A + (size_t)(bm0 + ar) * K + k0 + ac);
            if (!TB)
                bv2 = *reinterpret_cast<const float4*>(B + (size_t)(k0 + bk) * N + bn0 + bc);
            else
                bv2 = *reinterpret_cast<const float4*>(B + (size_t)(bn0 + ar) * K + k0 + ac);
        }

        #pragma unroll
        for (int k = 0; k < 16; k++) {
            float4 a4 = *reinterpret_cast<const float4*>(&As[buf][k][tr]);
            ull b01 = *reinterpret_cast<const ull*>(&Bs[buf][k][tc]);
            ull b23 = *reinterpret_cast<const ull*>(&Bs[buf][k][tc+2]);
            ull a0 = dup2(a4.x), a1 = dup2(a4.y), a2 = dup2(a4.z), a3 = dup2(a4.w);
            ffma2(acc[0][0], a0, b01); ffma2(acc[0][1], a0, b23);
            ffma2(acc[1][0], a1, b01); ffma2(acc[1][1], a1, b23);
            ffma2(acc[2][0], a2, b01); ffma2(acc[2][1], a2, b23);
            ffma2(acc[3][0], a3, b01); ffma2(acc[3][1], a3, b23);
        }

        if (more) {
            int nb = buf ^ 1;
            As[nb][ac+0][ar] = av2.x; As[nb][ac+1][ar] = av2.y;
            As[nb][ac+2][ar] = av2.z; As[nb][ac+3][ar] = av2.w;
            if (!TB) {
                *reinterpret_cast<float4*>(&Bs[nb][bk][bc]) = bv2;
            } else {
                Bs[nb][ac+0][ar] = bv2.x; Bs[nb][ac+1][ar] = bv2.y;
                Bs[nb][ac+2][ar] = bv2.z; Bs[nb][ac+3][ar] = bv2.w;
            }
        }
        buf ^= 1;
    }

    float* Cp = Cout + (size_t)blockIdx.z * M * N;
    #pragma unroll
    for (int i = 0; i < 4; i++) {
        int m = bm0 + tr + i;
        float v0, v1, v2, v3;
        unpack2(acc[i][0], v0, v1);
        unpack2(acc[i][1], v2, v3);
        float4 o = make_float4(v0, v1, v2, v3);
        *reinterpret_cast<float4*>(Cp + (size_t)m * N + bn0 + tc) = o;
    }
}

// -------- split-K reduce (8) + epilogue for Z: relu(.+a), also UU = h.*Z --------
__global__ __launch_bounds__(256)
void reduceZ(const float* __restrict__ h, const float* __restrict__ a)
{
    int idx = blockIdx.x * 256 + threadIdx.x;     // float4 index, 32768 total
    int e = idx * 4;
    int col = e & (HH - 1);
    float4 s = *reinterpret_cast<const float4*>(g_sp + e);
    #pragma unroll
    for (int sp = 1; sp < 8; sp++) {
        float4 t = *reinterpret_cast<const float4*>(g_sp + (size_t)sp*TT*HH + e);
        s.x += t.x; s.y += t.y; s.z += t.z; s.w += t.w;
    }
    float4 bi = *reinterpret_cast<const float4*>(a + col);
    float4 hv = *reinterpret_cast<const float4*>(h + e);
    float4 z;
    z.x = fmaxf(s.x + bi.x, 0.f);
    z.y = fmaxf(s.y + bi.y, 0.f);
    z.z = fmaxf(s.z + bi.z, 0.f);
    z.w = fmaxf(s.w + bi.w, 0.f);
    *reinterpret_cast<float4*>(g_Z + e) = z;
    float4 u = make_float4(hv.x*z.x, hv.y*z.y, hv.z*z.z, hv.w*z.w);
    *reinterpret_cast<float4*>(g_UU + e) = u;
}

// -------- split-K reduce (8) + bias for P --------
__global__ __launch_bounds__(256)
void reduceP(const float* __restrict__ b)
{
    int idx = blockIdx.x * 256 + threadIdx.x;
    int e = idx * 4;
    int col = e & (HH - 1);
    float4 s = *reinterpret_cast<const float4*>(g_sp + e);
    #pragma unroll
    for (int sp = 1; sp < 8; sp++) {
        float4 t = *reinterpret_cast<const float4*>(g_sp + (size_t)sp*TT*HH + e);
        s.x += t.x; s.y += t.y; s.z += t.z; s.w += t.w;
    }
    float4 bi = *reinterpret_cast<const float4*>(b + col);
    float4 p = make_float4(s.x + bi.x, s.y + bi.y, s.z + bi.z, s.w + bi.w);
    *reinterpret_cast<float4*>(g_P + e) = p;
}

// -------- split-K reduce (16) for C: strict-lower mask + kappa --------
__global__ __launch_bounds__(256)
void reduceC()
{
    int idx = blockIdx.x * 256 + threadIdx.x;    // float4 index, 16384 total
    int e = idx * 4;
    int m = e >> 8;               // /TT
    int n0 = e & (TT - 1);
    float4 s = *reinterpret_cast<const float4*>(g_spC + e);
    #pragma unroll
    for (int sp = 1; sp < 16; sp++) {
        float4 t = *reinterpret_cast<const float4*>(g_spC + (size_t)sp*TT*TT + e);
        s.x += t.x; s.y += t.y; s.z += t.z; s.w += t.w;
    }
    float4 kp = *reinterpret_cast<const float4*>(g_kappa + n0);
    float4 o;
    o.x = (n0+0 < m) ? (s.x + kp.x) : 0.f;
    o.y = (n0+1 < m) ? (s.y + kp.y) : 0.f;
    o.z = (n0+2 < m) ? (s.z + kp.z) : 0.f;
    o.w = (n0+3 < m) ? (s.w + kp.w) : 0.f;
    *reinterpret_cast<float4*>(g_C + e) = o;
}

// -------- split-K reduce (4) for M --------
__global__ __launch_bounds__(256)
void reduceM()
{
    int idx = blockIdx.x * 256 + threadIdx.x;    // float4 index, 65536 total
    int e = idx * 4;
    float4 s = *reinterpret_cast<const float4*>(g_sp + e);
    #pragma unroll
    for (int sp = 1; sp < 4; sp++) {
        float4 t = *reinterpret_cast<const float4*>(g_sp + (size_t)sp*TT*2*HH + e);
        s.x += t.x; s.y += t.y; s.z += t.z; s.w += t.w;
    }
    *reinterpret_cast<float4*>(g_M + e) = s;
}

// -------- per-row: LN -> softmax-CE backward -> LN backward -> d_t, kappa --------
__global__ __launch_bounds__(256)
void grad_rows(const float* __restrict__ P, const float* __restrict__ h,
               const float* __restrict__ gamma, const float* __restrict__ beta,
               const int* __restrict__ tgt)
{
    __shared__ float sb[16];
    const int t = blockIdx.x;
    const int j0 = threadIdx.x, j1 = threadIdx.x + 256;
    const float* pr = P + t * HH;

    float p0 = pr[j0], p1 = pr[j1];
    float m  = blockReduceSum256(p0 + p1, sb) * (1.f / HH);
    float d0 = p0 - m, d1 = p1 - m;
    float v  = blockReduceSum256(d0*d0 + d1*d1, sb) * (1.f / HH);
    float rs = rsqrtf(v + 1e-5f);
    float x0 = d0 * rs, x1 = d1 * rs;

    float ga0 = gamma[j0], ga1 = gamma[j1];
    float y0 = x0 * ga0 + beta[j0], y1 = x1 * ga1 + beta[j1];

    float ymax = blockReduceMax256(fmaxf(y0, y1), sb);
    float e0 = expf(y0 - ymax), e1 = expf(y1 - ymax);
    float inv = 1.f / blockReduceSum256(e0 + e1, sb);

    int target = tgt[t];
    float gg0 = e0 * inv - (j0 == target ? 1.f : 0.f);
    float gg1 = e1 * inv - (j1 == target ? 1.f : 0.f);
    float gh0 = ga0 * gg0, gh1 = ga1 * gg1;

    float mg  = blockReduceSum256(gh0 + gh1, sb) * (1.f / HH);
    float mgx = blockReduceSum256(gh0*x0 + gh1*x1, sb) * (1.f / HH);

    g_DE[t*2*HH + j0] = rs * (gh0 - mg - x0 * mgx);
    g_DE[t*2*HH + j1] = rs * (gh1 - mg - x1 * mgx);

    float hv0 = h[t*HH + j0], hv1 = h[t*HH + j1];
    float ks = blockReduceSum256(hv0 + hv1, sb);
    if (threadIdx.x == 0) g_kappa[t] = ks;
}

// -------- parallel cumsum over t, pass A: local prefix + chunk totals --------
__global__ __launch_bounds__(128)
void scanA(const float* __restrict__ h)
{
    const int q  = blockIdx.x * 128 + threadIdx.x;
    const int t0 = blockIdx.y * TCH;
    float acc = 0.f;
    #pragma unroll
    for (int tt = 0; tt < TCH; tt++) {
        acc += h[(t0 + tt) * HH + q];
        g_S[(t0 + tt) * HH + q] = acc;
    }
    g_part[blockIdx.y * HH + q] = acc;
}

// -------- pass B: add chunk offsets, write E = S .* D --------
__global__ __launch_bounds__(128)
void scanB()
{
    const int q  = blockIdx.x * 128 + threadIdx.x;
    const int cb = blockIdx.y;
    const int t0 = cb * TCH;
    float off = 0.f;
    for (int c = 0; c < cb; c++) off += g_part[c * HH + q];
    #pragma unroll
    for (int tt = 0; tt < TCH; tt++) {
        int t = t0 + tt;
        float s = g_S[t * HH + q] + off;
        g_S[t * HH + q] = s;
        g_DE[t*2*HH + HH + q] = s * g_DE[t*2*HH + q];
    }
}

// -------- assemble pre, final LayerNorm --------
__global__ __launch_bounds__(256)
void final_rows(const float* __restrict__ gamma, const float* __restrict__ beta,
                float* __restrict__ out)
{
    __shared__ float sb[16];
    const int t = blockIdx.x;
    const int j0 = threadIdx.x, j1 = threadIdx.x + 256;

    float pre0 = g_P[t*HH + j0]
               - g_S[t*HH + j0] * g_M[t*2*HH + j0]
               + g_M[t*2*HH + HH + j0];
    float pre1 = g_P[t*HH + j1]
               - g_S[t*HH + j1] * g_M[t*2*HH + j1]
               + g_M[t*2*HH + HH + j1];

    float m  = blockReduceSum256(pre0 + pre1, sb) * (1.f / HH);
    float d0 = pre0 - m, d1 = pre1 - m;
    float v  = blockReduceSum256(d0*d0 + d1*d1, sb) * (1.f / HH);
    float rs = rsqrtf(v + 1e-5f);

    out[t*HH + j0] = d0 * rs * gamma[j0] + beta[j0];
    out[t*HH + j1] = d1 * rs * gamma[j1] + beta[j1];
}

extern "C" void kernel_launch(void* const* d_in, const int* in_sizes, int n_in,
                              void* d_out, int out_size)
{
    const float* h     = (const float*)d_in[0];
    const float* U     = (const float*)d_in[1];
    const float* W     = (const float*)d_in[2];
    const float* a     = (const float*)d_in[3];
    const float* b     = (const float*)d_in[4];
    const float* gamma = (const float*)d_in[5];
    const float* beta  = (const float*)d_in[6];
    const int*   tgt   = (const int*)d_in[7];
    float* out = (float*)d_out;

    static float *pZ = nullptr, *pP, *pUU, *pDE, *pM, *pC, *pSp, *pSpC;
    if (!pZ) {
        cudaGetSymbolAddress((void**)&pZ,   g_Z);
        cudaGetSymbolAddress((void**)&pP,   g_P);
        cudaGetSymbolAddress((void**)&pUU,  g_UU);
        cudaGetSymbolAddress((void**)&pDE,  g_DE);
        cudaGetSymbolAddress((void**)&pM,   g_M);
        cudaGetSymbolAddress((void**)&pC,   g_C);
        cudaGetSymbolAddress((void**)&pSp,  g_sp);
        cudaGetSymbolAddress((void**)&pSpC, g_spC);
    }

    // Z = relu(h @ U + a): split-K 8 -> 256 blocks, then reduce (+ UU = h.*Z)
    gemm_f2<false><<<dim3(HH/64, TT/64, 8), 256>>>(h, U, pSp, TT, HH, HH, HH/8);
    reduceZ<<<128, 256>>>(h, a);
    // C partials: z_t.(h_i.*z_i), split-K 16 -> 256 blocks
    gemm_f2<true><<<dim3(TT/64, TT/64, 16), 256>>>(pZ, pUU, pSpC, TT, TT, HH, HH/16);
    // P = Z @ W + b: split-K 8 -> 256 blocks, then reduce
    gemm_f2<false><<<dim3(HH/64, TT/64, 8), 256>>>(pZ, W, pSp, TT, HH, HH, HH/8);
    reduceP<<<128, 256>>>(b);
    // d_t rows, kappa
    grad_rows<<<TT, 256>>>(pP, h, gamma, beta, tgt);
    // S = cumsum(h) (two-pass), E = S.*D
    scanA<<<dim3(HH/128, NCHUNK), 128>>>(h);
    scanB<<<dim3(HH/128, NCHUNK), 128>>>();
    // C' = mask(sum partials) + kappa
    reduceC<<<64, 256>>>();
    // M partials = C' @ [D | E]: split-K 4 -> 256 blocks, then reduce
    gemm_f2<false><<<dim3(2*HH/64, TT/64, 4), 256>>>(pC, pDE, pSp, TT, 2*HH, TT, TT/4);
    reduceM<<<256, 256>>>();
    // pre = P - S.*M1 + M2; out = LN(pre)
    final_rows<<<TT, 256>>>(gamma, beta, out);
}